// round 12
// baseline (speedup 1.0000x reference)
#include <cuda_runtime.h>
#include <cuda_fp16.h>
#include <cstdint>

#define D 128
#define BM 64
#define N_MAX 100000
#define E_MAX 3200000
#define CAP 128          // bucket capacity (Poisson(32) -> P(>128)~1e-40) — R9 proven value

// ---- packed f32x2 helpers --------------------------------------------------
#define FMA_F32X2(d, a, b, c) \
    asm("fma.rn.f32x2 %0, %1, %2, %3;" : "=l"(d) : "l"(a), "l"(b), "l"(c))
#define ADD_F32X2(d, a, b) \
    asm("add.rn.f32x2 %0, %1, %2;" : "=l"(d) : "l"(a), "l"(b))
#define PACK_DUP_F32X2(out, r) \
    asm("mov.b64 %0, {%1, %1};" : "=l"(out) : "r"(r))

static __device__ __forceinline__ unsigned h2_to_u32(__half2 h) {
    return *reinterpret_cast<unsigned*>(&h);
}
static __device__ __forceinline__ __half2 u32_to_h2(unsigned u) {
    return *reinterpret_cast<__half2*>(&u);
}

// Scratch
__device__ uint2  g_hh[N_MAX * 32];          // h in fp16 (4 halves / lane-slot)
__device__ float4 g_wt4[D * D / 4];          // W^T
__device__ int    g_cnt[N_MAX];              // per-node cursor
__device__ int2   g_bkt[(long long)N_MAX * CAP];  // (src, w-bits) buckets
__device__ int    g_ovf_cnt;                 // overflow edges (expected 0)
__device__ int4   g_ovf[4096];               // (src, dst, w-bits, pad)

// ---------------------------------------------------------------------------
__global__ void zero_kernel(int n_nodes) {
    int i = blockIdx.x * blockDim.x + threadIdx.x;
    if (i < n_nodes) g_cnt[i] = 0;
    if (i == 0) g_ovf_cnt = 0;
}

__global__ void transpose_w_kernel(const float* __restrict__ W) {
    int idx = blockIdx.x * blockDim.x + threadIdx.x;
    int j = idx >> 7;
    int k = idx & (D - 1);
    ((float*)g_wt4)[k * D + j] = W[j * D + k];
}

// single-pass placement into fixed-stride buckets (R9 scalar form)
__global__ void place_kernel(const int* __restrict__ src,
                             const int* __restrict__ dst,
                             const float* __restrict__ w,
                             int n_edges) {
    int t = blockIdx.x * blockDim.x + threadIdx.x;
    int e = t * 4;
    #pragma unroll
    for (int j = 0; j < 4; j++) {
        int i = e + j;
        if (i >= n_edges) return;
        int s = src[i];
        int d = dst[i];
        int wb = __float_as_int(w[i]);
        int pos = atomicAdd(&g_cnt[d], 1);
        if (pos < CAP) {
            g_bkt[(long long)d * CAP + pos] = make_int2(s, wb);
        } else {
            int o = atomicAdd(&g_ovf_cnt, 1);
            if (o < 4096) g_ovf[o] = make_int4(s, d, wb, 0);
        }
    }
}

// ---------------------------------------------------------------------------
// GEMM: h = x @ W^T + b with packed f32x2 FMA; epilogue rounds h to fp16.
// ---------------------------------------------------------------------------
__global__ __launch_bounds__(256, 2)
void gemm_kernel(const float* __restrict__ x, const float* __restrict__ bias,
                 int n_rows) {
    extern __shared__ float4 smem4[];
    float4* Ws4 = smem4;                 // [128][32] f4
    float4* Xs4 = smem4 + D * (D / 4);   // [64][32]  f4

    const int tid  = threadIdx.x;
    const int row0 = blockIdx.x * BM;
    const int rows = min(BM, n_rows - row0);

    #pragma unroll
    for (int i = 0; i < (D * D / 4) / 256; i++)
        Ws4[tid + i * 256] = g_wt4[tid + i * 256];
    {
        const float4* x4 = (const float4*)(x + (long long)row0 * D);
        const int nf4 = rows * (D / 4);
        for (int i = tid; i < nf4; i += 256)
            Xs4[i] = x4[i];
    }
    __syncthreads();

    const int warp = tid >> 5;
    const int lane = tid & 31;
    const int r0 = warp * 8;

    const ulonglong2* Ws2 = (const ulonglong2*)Ws4;

    unsigned long long acc[8][2];
    #pragma unroll
    for (int i = 0; i < 8; i++) { acc[i][0] = 0ull; acc[i][1] = 0ull; }

    #pragma unroll 4
    for (int k = 0; k < D; k += 4) {
        ulonglong2 wv0 = Ws2[(k + 0) * 32 + lane];
        ulonglong2 wv1 = Ws2[(k + 1) * 32 + lane];
        ulonglong2 wv2 = Ws2[(k + 2) * 32 + lane];
        ulonglong2 wv3 = Ws2[(k + 3) * 32 + lane];
        #pragma unroll
        for (int i = 0; i < 8; i++) {
            float4 xv = Xs4[(r0 + i) * 32 + (k >> 2)];  // warp broadcast
            unsigned long long xd;
            PACK_DUP_F32X2(xd, __float_as_uint(xv.x));
            FMA_F32X2(acc[i][0], xd, wv0.x, acc[i][0]);
            FMA_F32X2(acc[i][1], xd, wv0.y, acc[i][1]);
            PACK_DUP_F32X2(xd, __float_as_uint(xv.y));
            FMA_F32X2(acc[i][0], xd, wv1.x, acc[i][0]);
            FMA_F32X2(acc[i][1], xd, wv1.y, acc[i][1]);
            PACK_DUP_F32X2(xd, __float_as_uint(xv.z));
            FMA_F32X2(acc[i][0], xd, wv2.x, acc[i][0]);
            FMA_F32X2(acc[i][1], xd, wv2.y, acc[i][1]);
            PACK_DUP_F32X2(xd, __float_as_uint(xv.w));
            FMA_F32X2(acc[i][0], xd, wv3.x, acc[i][0]);
            FMA_F32X2(acc[i][1], xd, wv3.y, acc[i][1]);
        }
    }

    ulonglong2 bv = ((const ulonglong2*)bias)[lane];
    #pragma unroll
    for (int i = 0; i < 8; i++) {
        int r = r0 + i;
        if (r < rows) {
            ulonglong2 o;
            ADD_F32X2(o.x, acc[i][0], bv.x);
            ADD_F32X2(o.y, acc[i][1], bv.y);
            float2 p0 = *(float2*)&o.x;
            float2 p1 = *(float2*)&o.y;
            uint2 hh;
            hh.x = h2_to_u32(__floats2half2_rn(p0.x, p0.y));
            hh.y = h2_to_u32(__floats2half2_rn(p1.x, p1.y));
            g_hh[(long long)(row0 + r) * 32 + lane] = hh;
        }
    }
}

// ---------------------------------------------------------------------------
// aggregate (R9 shape + seg prefetch): one warp per node, lane owns 4 cols.
// Double-buffer the 8 edge descriptors so seg-read latency overlaps the
// gather latency of the previous batch (breaks the dependent-load chain).
// ---------------------------------------------------------------------------
__global__ __launch_bounds__(256)
void aggregate_kernel(float* __restrict__ out, int n_nodes) {
    int node = (blockIdx.x * 256 + threadIdx.x) >> 5;
    int lane = threadIdx.x & 31;
    if (node >= n_nodes) return;

    const int2* seg = g_bkt + (long long)node * CAP;
    int end = min(g_cnt[node], CAP);

    float4 acc = make_float4(0.f, 0.f, 0.f, 0.f);

    int i = 0;
    int2 ed[8];
    bool have = (i + 8 <= end);
    if (have) {
        #pragma unroll
        for (int j = 0; j < 8; j++) ed[j] = seg[j];
    }
    while (have) {
        int ni = i + 8;
        bool havenext = (ni + 8 <= end);
        int2 ednext[8];
        if (havenext) {
            #pragma unroll
            for (int j = 0; j < 8; j++) ednext[j] = seg[ni + j];  // prefetch
        }
        uint2 hv[8];
        #pragma unroll
        for (int j = 0; j < 8; j++) hv[j] = g_hh[(long long)ed[j].x * 32 + lane];
        #pragma unroll
        for (int j = 0; j < 8; j++) {
            float wv = __int_as_float(ed[j].y);
            float2 a  = __half22float2(u32_to_h2(hv[j].x));
            float2 bq = __half22float2(u32_to_h2(hv[j].y));
            acc.x += a.x * wv; acc.y += a.y * wv;
            acc.z += bq.x * wv; acc.w += bq.y * wv;
        }
        i = ni;
        have = havenext;
        if (havenext) {
            #pragma unroll
            for (int j = 0; j < 8; j++) ed[j] = ednext[j];
        }
    }
    for (; i < end; i++) {
        int2 e = seg[i];
        float wv = __int_as_float(e.y);
        uint2 hv = g_hh[(long long)e.x * 32 + lane];
        float2 a  = __half22float2(u32_to_h2(hv.x));
        float2 bq = __half22float2(u32_to_h2(hv.y));
        acc.x += a.x * wv; acc.y += a.y * wv; acc.z += bq.x * wv; acc.w += bq.y * wv;
    }

    ((float4*)out)[(long long)node * 32 + lane] = acc;
}

// ---------------------------------------------------------------------------
// fixup: overflow edges (expected 0) via vector reductions.
// ---------------------------------------------------------------------------
__global__ void fixup_kernel(float* __restrict__ out) {
    int n = min(g_ovf_cnt, 4096);
    int lane = threadIdx.x & 31;
    int wid_global = (blockIdx.x * blockDim.x + threadIdx.x) >> 5;
    int nwarps = (gridDim.x * blockDim.x) >> 5;
    for (int e = wid_global; e < n; e += nwarps) {
        int4 ov = g_ovf[e];
        float wv = __int_as_float(ov.z);
        uint2 hv = g_hh[(long long)ov.x * 32 + lane];
        float2 a  = __half22float2(u32_to_h2(hv.x));
        float2 bq = __half22float2(u32_to_h2(hv.y));
        float* p = out + (long long)ov.y * D + lane * 4;
        asm volatile("red.global.add.v4.f32 [%0], {%1, %2, %3, %4};"
                     :: "l"(p), "f"(a.x * wv), "f"(a.y * wv),
                        "f"(bq.x * wv), "f"(bq.y * wv) : "memory");
    }
}

// ---------------------------------------------------------------------------
extern "C" void kernel_launch(void* const* d_in, const int* in_sizes, int n_in,
                              void* d_out, int out_size) {
    const float* x   = (const float*)d_in[0];
    const float* w   = (const float*)d_in[1];
    const float* W   = (const float*)d_in[2];
    const float* b   = (const float*)d_in[3];
    const int*   src = (const int*)d_in[4];   // int32 (JAX x64 disabled)
    const int*   dst = (const int*)d_in[5];

    int N = in_sizes[0] / D;
    int E = in_sizes[1];
    float* out = (float*)d_out;

    int nb_nodes = (N + 255) / 256;
    int nb_e4    = (E + 4 * 256 - 1) / (4 * 256);

    cudaStream_t s2;
    cudaStreamCreate(&s2);
    cudaEvent_t evFork, evJoin;
    cudaEventCreateWithFlags(&evFork, cudaEventDisableTiming);
    cudaEventCreateWithFlags(&evJoin, cudaEventDisableTiming);

    cudaEventRecord(evFork, 0);
    cudaStreamWaitEvent(s2, evFork, 0);

    transpose_w_kernel<<<(D * D) / 256, 256, 0, s2>>>(W);
    const int smem_bytes = (D * D + BM * D) * sizeof(float);  // 96 KB
    cudaFuncSetAttribute(gemm_kernel,
                         cudaFuncAttributeMaxDynamicSharedMemorySize, smem_bytes);
    gemm_kernel<<<(N + BM - 1) / BM, 256, smem_bytes, s2>>>(x, b, N);
    cudaEventRecord(evJoin, s2);

    zero_kernel<<<nb_nodes, 256>>>(N);
    place_kernel<<<nb_e4, 256>>>(src, dst, w, E);

    cudaStreamWaitEvent(0, evJoin, 0);

    int nb_agg = (N * 32 + 255) / 256;   // one warp per node
    aggregate_kernel<<<nb_agg, 256>>>(out, N);
    fixup_kernel<<<16, 256>>>(out);

    cudaStreamCaptureStatus st = cudaStreamCaptureStatusNone;
    cudaStreamIsCapturing(0, &st);
    if (st == cudaStreamCaptureStatusNone) {
        cudaStreamDestroy(s2);
        cudaEventDestroy(evFork);
        cudaEventDestroy(evJoin);
    }
}

// round 13
// speedup vs baseline: 1.1748x; 1.1748x over previous
#include <cuda_runtime.h>
#include <cuda_fp16.h>
#include <cstdint>

#define D 128
#define BM 64
#define N_MAX 100000
#define E_MAX 3200000
#define CAP 64           // ONLY change vs R9: 128 -> 64 (fits L2; fixup covers overflow)

// ---- packed f32x2 helpers --------------------------------------------------
#define FMA_F32X2(d, a, b, c) \
    asm("fma.rn.f32x2 %0, %1, %2, %3;" : "=l"(d) : "l"(a), "l"(b), "l"(c))
#define ADD_F32X2(d, a, b) \
    asm("add.rn.f32x2 %0, %1, %2;" : "=l"(d) : "l"(a), "l"(b))
#define PACK_DUP_F32X2(out, r) \
    asm("mov.b64 %0, {%1, %1};" : "=l"(out) : "r"(r))

static __device__ __forceinline__ unsigned h2_to_u32(__half2 h) {
    return *reinterpret_cast<unsigned*>(&h);
}
static __device__ __forceinline__ __half2 u32_to_h2(unsigned u) {
    return *reinterpret_cast<__half2*>(&u);
}

// Scratch
__device__ uint2  g_hh[N_MAX * 32];          // h in fp16 (4 halves / lane-slot)
__device__ float4 g_wt4[D * D / 4];          // W^T
__device__ int    g_cnt[N_MAX];              // per-node cursor
__device__ int2   g_bkt[(long long)N_MAX * CAP];  // (src, w-bits) buckets (51.2 MB)
__device__ int    g_ovf_cnt;                 // overflow edges (expected ~0)
__device__ int4   g_ovf[4096];               // (src, dst, w-bits, pad)

// ---------------------------------------------------------------------------
__global__ void zero_kernel(int n_nodes) {
    int i = blockIdx.x * blockDim.x + threadIdx.x;
    if (i < n_nodes) g_cnt[i] = 0;
    if (i == 0) g_ovf_cnt = 0;
}

__global__ void transpose_w_kernel(const float* __restrict__ W) {
    int idx = blockIdx.x * blockDim.x + threadIdx.x;
    int j = idx >> 7;
    int k = idx & (D - 1);
    ((float*)g_wt4)[k * D + j] = W[j * D + k];
}

// single-pass placement into fixed-stride buckets (R9 scalar form)
__global__ void place_kernel(const int* __restrict__ src,
                             const int* __restrict__ dst,
                             const float* __restrict__ w,
                             int n_edges) {
    int t = blockIdx.x * blockDim.x + threadIdx.x;
    int e = t * 4;
    #pragma unroll
    for (int j = 0; j < 4; j++) {
        int i = e + j;
        if (i >= n_edges) return;
        int s = src[i];
        int d = dst[i];
        int wb = __float_as_int(w[i]);
        int pos = atomicAdd(&g_cnt[d], 1);
        if (pos < CAP) {
            g_bkt[(long long)d * CAP + pos] = make_int2(s, wb);
        } else {
            int o = atomicAdd(&g_ovf_cnt, 1);
            if (o < 4096) g_ovf[o] = make_int4(s, d, wb, 0);
        }
    }
}

// ---------------------------------------------------------------------------
// GEMM: h = x @ W^T + b with packed f32x2 FMA; epilogue rounds h to fp16.
// ---------------------------------------------------------------------------
__global__ __launch_bounds__(256, 2)
void gemm_kernel(const float* __restrict__ x, const float* __restrict__ bias,
                 int n_rows) {
    extern __shared__ float4 smem4[];
    float4* Ws4 = smem4;                 // [128][32] f4
    float4* Xs4 = smem4 + D * (D / 4);   // [64][32]  f4

    const int tid  = threadIdx.x;
    const int row0 = blockIdx.x * BM;
    const int rows = min(BM, n_rows - row0);

    #pragma unroll
    for (int i = 0; i < (D * D / 4) / 256; i++)
        Ws4[tid + i * 256] = g_wt4[tid + i * 256];
    {
        const float4* x4 = (const float4*)(x + (long long)row0 * D);
        const int nf4 = rows * (D / 4);
        for (int i = tid; i < nf4; i += 256)
            Xs4[i] = x4[i];
    }
    __syncthreads();

    const int warp = tid >> 5;
    const int lane = tid & 31;
    const int r0 = warp * 8;

    const ulonglong2* Ws2 = (const ulonglong2*)Ws4;

    unsigned long long acc[8][2];
    #pragma unroll
    for (int i = 0; i < 8; i++) { acc[i][0] = 0ull; acc[i][1] = 0ull; }

    #pragma unroll 4
    for (int k = 0; k < D; k += 4) {
        ulonglong2 wv0 = Ws2[(k + 0) * 32 + lane];
        ulonglong2 wv1 = Ws2[(k + 1) * 32 + lane];
        ulonglong2 wv2 = Ws2[(k + 2) * 32 + lane];
        ulonglong2 wv3 = Ws2[(k + 3) * 32 + lane];
        #pragma unroll
        for (int i = 0; i < 8; i++) {
            float4 xv = Xs4[(r0 + i) * 32 + (k >> 2)];  // warp broadcast
            unsigned long long xd;
            PACK_DUP_F32X2(xd, __float_as_uint(xv.x));
            FMA_F32X2(acc[i][0], xd, wv0.x, acc[i][0]);
            FMA_F32X2(acc[i][1], xd, wv0.y, acc[i][1]);
            PACK_DUP_F32X2(xd, __float_as_uint(xv.y));
            FMA_F32X2(acc[i][0], xd, wv1.x, acc[i][0]);
            FMA_F32X2(acc[i][1], xd, wv1.y, acc[i][1]);
            PACK_DUP_F32X2(xd, __float_as_uint(xv.z));
            FMA_F32X2(acc[i][0], xd, wv2.x, acc[i][0]);
            FMA_F32X2(acc[i][1], xd, wv2.y, acc[i][1]);
            PACK_DUP_F32X2(xd, __float_as_uint(xv.w));
            FMA_F32X2(acc[i][0], xd, wv3.x, acc[i][0]);
            FMA_F32X2(acc[i][1], xd, wv3.y, acc[i][1]);
        }
    }

    ulonglong2 bv = ((const ulonglong2*)bias)[lane];
    #pragma unroll
    for (int i = 0; i < 8; i++) {
        int r = r0 + i;
        if (r < rows) {
            ulonglong2 o;
            ADD_F32X2(o.x, acc[i][0], bv.x);
            ADD_F32X2(o.y, acc[i][1], bv.y);
            float2 p0 = *(float2*)&o.x;
            float2 p1 = *(float2*)&o.y;
            uint2 hh;
            hh.x = h2_to_u32(__floats2half2_rn(p0.x, p0.y));
            hh.y = h2_to_u32(__floats2half2_rn(p1.x, p1.y));
            g_hh[(long long)(row0 + r) * 32 + lane] = hh;
        }
    }
}

// ---------------------------------------------------------------------------
// aggregate (exact R9 shape): one warp per node, lane owns 4 columns.
// fp16 gather (8B/lane), fp32 accum, 8-way unroll, plain float4 store.
// ---------------------------------------------------------------------------
__global__ __launch_bounds__(256)
void aggregate_kernel(float* __restrict__ out, int n_nodes) {
    int node = (blockIdx.x * 256 + threadIdx.x) >> 5;
    int lane = threadIdx.x & 31;
    if (node >= n_nodes) return;

    const int2* seg = g_bkt + (long long)node * CAP;
    int cnt = g_cnt[node];
    int end = min(cnt, CAP);

    float4 acc = make_float4(0.f, 0.f, 0.f, 0.f);

    int i = 0;
    for (; i + 8 <= end; i += 8) {
        int2 ed[8];
        uint2 hv[8];
        #pragma unroll
        for (int j = 0; j < 8; j++) ed[j] = seg[i + j];
        #pragma unroll
        for (int j = 0; j < 8; j++) hv[j] = g_hh[(long long)ed[j].x * 32 + lane];
        #pragma unroll
        for (int j = 0; j < 8; j++) {
            float wv = __int_as_float(ed[j].y);
            float2 a  = __half22float2(u32_to_h2(hv[j].x));
            float2 bq = __half22float2(u32_to_h2(hv[j].y));
            acc.x += a.x * wv; acc.y += a.y * wv;
            acc.z += bq.x * wv; acc.w += bq.y * wv;
        }
    }
    for (; i < end; i++) {
        int2 e = seg[i];
        float wv = __int_as_float(e.y);
        uint2 hv = g_hh[(long long)e.x * 32 + lane];
        float2 a  = __half22float2(u32_to_h2(hv.x));
        float2 bq = __half22float2(u32_to_h2(hv.y));
        acc.x += a.x * wv; acc.y += a.y * wv; acc.z += bq.x * wv; acc.w += bq.y * wv;
    }

    ((float4*)out)[(long long)node * 32 + lane] = acc;
}

// ---------------------------------------------------------------------------
// fixup: overflow edges (expected ~0) via vector reductions.
// ---------------------------------------------------------------------------
__global__ void fixup_kernel(float* __restrict__ out) {
    int n = min(g_ovf_cnt, 4096);
    int lane = threadIdx.x & 31;
    int wid_global = (blockIdx.x * blockDim.x + threadIdx.x) >> 5;
    int nwarps = (gridDim.x * blockDim.x) >> 5;
    for (int e = wid_global; e < n; e += nwarps) {
        int4 ov = g_ovf[e];
        float wv = __int_as_float(ov.z);
        uint2 hv = g_hh[(long long)ov.x * 32 + lane];
        float2 a  = __half22float2(u32_to_h2(hv.x));
        float2 bq = __half22float2(u32_to_h2(hv.y));
        float* p = out + (long long)ov.y * D + lane * 4;
        asm volatile("red.global.add.v4.f32 [%0], {%1, %2, %3, %4};"
                     :: "l"(p), "f"(a.x * wv), "f"(a.y * wv),
                        "f"(bq.x * wv), "f"(bq.y * wv) : "memory");
    }
}

// ---------------------------------------------------------------------------
extern "C" void kernel_launch(void* const* d_in, const int* in_sizes, int n_in,
                              void* d_out, int out_size) {
    const float* x   = (const float*)d_in[0];
    const float* w   = (const float*)d_in[1];
    const float* W   = (const float*)d_in[2];
    const float* b   = (const float*)d_in[3];
    const int*   src = (const int*)d_in[4];   // int32 (JAX x64 disabled)
    const int*   dst = (const int*)d_in[5];

    int N = in_sizes[0] / D;
    int E = in_sizes[1];
    float* out = (float*)d_out;

    int nb_nodes = (N + 255) / 256;
    int nb_e4    = (E + 4 * 256 - 1) / (4 * 256);

    cudaStream_t s2;
    cudaStreamCreate(&s2);
    cudaEvent_t evFork, evJoin;
    cudaEventCreateWithFlags(&evFork, cudaEventDisableTiming);
    cudaEventCreateWithFlags(&evJoin, cudaEventDisableTiming);

    cudaEventRecord(evFork, 0);
    cudaStreamWaitEvent(s2, evFork, 0);

    transpose_w_kernel<<<(D * D) / 256, 256, 0, s2>>>(W);
    const int smem_bytes = (D * D + BM * D) * sizeof(float);  // 96 KB
    cudaFuncSetAttribute(gemm_kernel,
                         cudaFuncAttributeMaxDynamicSharedMemorySize, smem_bytes);
    gemm_kernel<<<(N + BM - 1) / BM, 256, smem_bytes, s2>>>(x, b, N);
    cudaEventRecord(evJoin, s2);

    zero_kernel<<<nb_nodes, 256>>>(N);
    place_kernel<<<nb_e4, 256>>>(src, dst, w, E);

    cudaStreamWaitEvent(0, evJoin, 0);

    int nb_agg = (N * 32 + 255) / 256;   // one warp per node
    aggregate_kernel<<<nb_agg, 256>>>(out, N);
    fixup_kernel<<<16, 256>>>(out);

    cudaStreamCaptureStatus st = cudaStreamCaptureStatusNone;
    cudaStreamIsCapturing(0, &st);
    if (st == cudaStreamCaptureStatusNone) {
        cudaStreamDestroy(s2);
        cudaEventDestroy(evFork);
        cudaEventDestroy(evJoin);
    }
}

// round 14
// speedup vs baseline: 1.1952x; 1.0173x over previous
#include <cuda_runtime.h>
#include <cuda_fp16.h>
#include <cstdint>

#define D 128
#define BM 64
#define N_MAX 100000
#define E_MAX 3200000
#define CAP 128          // proven best (R9)

// ---- packed f32x2 helpers --------------------------------------------------
#define FMA_F32X2(d, a, b, c) \
    asm("fma.rn.f32x2 %0, %1, %2, %3;" : "=l"(d) : "l"(a), "l"(b), "l"(c))
#define ADD_F32X2(d, a, b) \
    asm("add.rn.f32x2 %0, %1, %2;" : "=l"(d) : "l"(a), "l"(b))
#define PACK_DUP_F32X2(out, r) \
    asm("mov.b64 %0, {%1, %1};" : "=l"(out) : "r"(r))

static __device__ __forceinline__ unsigned h2_to_u32(__half2 h) {
    return *reinterpret_cast<unsigned*>(&h);
}
static __device__ __forceinline__ __half2 u32_to_h2(unsigned u) {
    return *reinterpret_cast<__half2*>(&u);
}

// Scratch
__device__ uint2  g_hh[N_MAX * 32];          // h in fp16 (4 halves / lane-slot)
__device__ float4 g_wt4[D * D / 4];          // W^T
__device__ int    g_cnt[N_MAX];              // per-node cursor
__device__ int2   g_bkt[(long long)N_MAX * CAP];  // (src, w-bits) buckets
__device__ int    g_ovf_cnt;                 // overflow edges (expected 0)
__device__ int4   g_ovf[4096];               // (src, dst, w-bits, pad)

// ---------------------------------------------------------------------------
__global__ void zero_kernel(int n_nodes) {
    int i = blockIdx.x * blockDim.x + threadIdx.x;
    if (i < n_nodes) g_cnt[i] = 0;
    if (i == 0) g_ovf_cnt = 0;
}

__global__ void transpose_w_kernel(const float* __restrict__ W) {
    int idx = blockIdx.x * blockDim.x + threadIdx.x;
    int j = idx >> 7;
    int k = idx & (D - 1);
    ((float*)g_wt4)[k * D + j] = W[j * D + k];
}

// ---------------------------------------------------------------------------
// FUSED kernel: interleaved heterogeneous blocks.
//   b % 3 == 0  -> GEMM tile b/3          (FMA-pipe-bound)
//   otherwise   -> place chunk b - b/3 -1 (L2/atomic-bound)
// One launch => guaranteed co-scheduling; no reliance on stream-fork capture.
// ---------------------------------------------------------------------------
__device__ __forceinline__ void gemm_block(
    const float* __restrict__ x, const float* __restrict__ bias,
    int n_rows, int blk)
{
    extern __shared__ float4 smem4[];
    float4* Ws4 = smem4;                 // [128][32] f4
    float4* Xs4 = smem4 + D * (D / 4);   // [64][32]  f4

    const int tid  = threadIdx.x;
    const int row0 = blk * BM;
    const int rows = min(BM, n_rows - row0);

    #pragma unroll
    for (int i = 0; i < (D * D / 4) / 256; i++)
        Ws4[tid + i * 256] = g_wt4[tid + i * 256];
    {
        const float4* x4 = (const float4*)(x + (long long)row0 * D);
        const int nf4 = rows * (D / 4);
        for (int i = tid; i < nf4; i += 256)
            Xs4[i] = x4[i];
    }
    __syncthreads();

    const int warp = tid >> 5;
    const int lane = tid & 31;
    const int r0 = warp * 8;

    const ulonglong2* Ws2 = (const ulonglong2*)Ws4;

    unsigned long long acc[8][2];
    #pragma unroll
    for (int i = 0; i < 8; i++) { acc[i][0] = 0ull; acc[i][1] = 0ull; }

    #pragma unroll 4
    for (int k = 0; k < D; k += 4) {
        ulonglong2 wv0 = Ws2[(k + 0) * 32 + lane];
        ulonglong2 wv1 = Ws2[(k + 1) * 32 + lane];
        ulonglong2 wv2 = Ws2[(k + 2) * 32 + lane];
        ulonglong2 wv3 = Ws2[(k + 3) * 32 + lane];
        #pragma unroll
        for (int i = 0; i < 8; i++) {
            float4 xv = Xs4[(r0 + i) * 32 + (k >> 2)];  // warp broadcast
            unsigned long long xd;
            PACK_DUP_F32X2(xd, __float_as_uint(xv.x));
            FMA_F32X2(acc[i][0], xd, wv0.x, acc[i][0]);
            FMA_F32X2(acc[i][1], xd, wv0.y, acc[i][1]);
            PACK_DUP_F32X2(xd, __float_as_uint(xv.y));
            FMA_F32X2(acc[i][0], xd, wv1.x, acc[i][0]);
            FMA_F32X2(acc[i][1], xd, wv1.y, acc[i][1]);
            PACK_DUP_F32X2(xd, __float_as_uint(xv.z));
            FMA_F32X2(acc[i][0], xd, wv2.x, acc[i][0]);
            FMA_F32X2(acc[i][1], xd, wv2.y, acc[i][1]);
            PACK_DUP_F32X2(xd, __float_as_uint(xv.w));
            FMA_F32X2(acc[i][0], xd, wv3.x, acc[i][0]);
            FMA_F32X2(acc[i][1], xd, wv3.y, acc[i][1]);
        }
    }

    ulonglong2 bv = ((const ulonglong2*)bias)[lane];
    #pragma unroll
    for (int i = 0; i < 8; i++) {
        int r = r0 + i;
        if (r < rows) {
            ulonglong2 o;
            ADD_F32X2(o.x, acc[i][0], bv.x);
            ADD_F32X2(o.y, acc[i][1], bv.y);
            float2 p0 = *(float2*)&o.x;
            float2 p1 = *(float2*)&o.y;
            uint2 hh;
            hh.x = h2_to_u32(__floats2half2_rn(p0.x, p0.y));
            hh.y = h2_to_u32(__floats2half2_rn(p1.x, p1.y));
            g_hh[(long long)(row0 + r) * 32 + lane] = hh;
        }
    }
}

__device__ __forceinline__ void place_block(
    const int* __restrict__ src, const int* __restrict__ dst,
    const float* __restrict__ w, int n_edges, int pidx)
{
    int t = pidx * 256 + threadIdx.x;
    int e = t * 4;
    #pragma unroll
    for (int j = 0; j < 4; j++) {
        int i = e + j;
        if (i >= n_edges) return;
        int s = src[i];
        int d = dst[i];
        int wb = __float_as_int(w[i]);
        int pos = atomicAdd(&g_cnt[d], 1);
        if (pos < CAP) {
            g_bkt[(long long)d * CAP + pos] = make_int2(s, wb);
        } else {
            int o = atomicAdd(&g_ovf_cnt, 1);
            if (o < 4096) g_ovf[o] = make_int4(s, d, wb, 0);
        }
    }
}

__global__ __launch_bounds__(256, 2)
void fused_gemm_place_kernel(const float* __restrict__ x,
                             const float* __restrict__ bias,
                             const int* __restrict__ src,
                             const int* __restrict__ dst,
                             const float* __restrict__ w,
                             int n_rows, int n_edges,
                             int nb_gemm, int nb_place) {
    int b = blockIdx.x;
    if (b % 3 == 0) {
        int gi = b / 3;
        if (gi < nb_gemm) gemm_block(x, bias, n_rows, gi);
    } else {
        int pi = b - b / 3 - 1;
        if (pi < nb_place) place_block(src, dst, w, n_edges, pi);
    }
}

// ---------------------------------------------------------------------------
// aggregate (exact R9 shape): one warp per node, lane owns 4 columns.
// ---------------------------------------------------------------------------
__global__ __launch_bounds__(256)
void aggregate_kernel(float* __restrict__ out, int n_nodes) {
    int node = (blockIdx.x * 256 + threadIdx.x) >> 5;
    int lane = threadIdx.x & 31;
    if (node >= n_nodes) return;

    const int2* seg = g_bkt + (long long)node * CAP;
    int cnt = g_cnt[node];
    int end = min(cnt, CAP);

    float4 acc = make_float4(0.f, 0.f, 0.f, 0.f);

    int i = 0;
    for (; i + 8 <= end; i += 8) {
        int2 ed[8];
        uint2 hv[8];
        #pragma unroll
        for (int j = 0; j < 8; j++) ed[j] = seg[i + j];
        #pragma unroll
        for (int j = 0; j < 8; j++) hv[j] = g_hh[(long long)ed[j].x * 32 + lane];
        #pragma unroll
        for (int j = 0; j < 8; j++) {
            float wv = __int_as_float(ed[j].y);
            float2 a  = __half22float2(u32_to_h2(hv[j].x));
            float2 bq = __half22float2(u32_to_h2(hv[j].y));
            acc.x += a.x * wv; acc.y += a.y * wv;
            acc.z += bq.x * wv; acc.w += bq.y * wv;
        }
    }
    for (; i < end; i++) {
        int2 e = seg[i];
        float wv = __int_as_float(e.y);
        uint2 hv = g_hh[(long long)e.x * 32 + lane];
        float2 a  = __half22float2(u32_to_h2(hv.x));
        float2 bq = __half22float2(u32_to_h2(hv.y));
        acc.x += a.x * wv; acc.y += a.y * wv; acc.z += bq.x * wv; acc.w += bq.y * wv;
    }

    ((float4*)out)[(long long)node * 32 + lane] = acc;
}

// ---------------------------------------------------------------------------
__global__ void fixup_kernel(float* __restrict__ out) {
    int n = min(g_ovf_cnt, 4096);
    int lane = threadIdx.x & 31;
    int wid_global = (blockIdx.x * blockDim.x + threadIdx.x) >> 5;
    int nwarps = (gridDim.x * blockDim.x) >> 5;
    for (int e = wid_global; e < n; e += nwarps) {
        int4 ov = g_ovf[e];
        float wv = __int_as_float(ov.z);
        uint2 hv = g_hh[(long long)ov.x * 32 + lane];
        float2 a  = __half22float2(u32_to_h2(hv.x));
        float2 bq = __half22float2(u32_to_h2(hv.y));
        float* p = out + (long long)ov.y * D + lane * 4;
        asm volatile("red.global.add.v4.f32 [%0], {%1, %2, %3, %4};"
                     :: "l"(p), "f"(a.x * wv), "f"(a.y * wv),
                        "f"(bq.x * wv), "f"(bq.y * wv) : "memory");
    }
}

// ---------------------------------------------------------------------------
extern "C" void kernel_launch(void* const* d_in, const int* in_sizes, int n_in,
                              void* d_out, int out_size) {
    const float* x   = (const float*)d_in[0];
    const float* w   = (const float*)d_in[1];
    const float* W   = (const float*)d_in[2];
    const float* b   = (const float*)d_in[3];
    const int*   src = (const int*)d_in[4];   // int32 (JAX x64 disabled)
    const int*   dst = (const int*)d_in[5];

    int N = in_sizes[0] / D;
    int E = in_sizes[1];
    float* out = (float*)d_out;

    int nb_nodes = (N + 255) / 256;
    int nb_gemm  = (N + BM - 1) / BM;              // 1563
    int nb_place = (E + 4 * 256 - 1) / (4 * 256);  // 3125
    // T = 3 * max(nb_gemm, ceil(nb_place/2)) covers both with b%3 interleave
    int half_p = (nb_place + 1) / 2;
    int T = 3 * (nb_gemm > half_p ? nb_gemm : half_p);

    zero_kernel<<<nb_nodes, 256>>>(N);
    transpose_w_kernel<<<(D * D) / 256, 256>>>(W);

    const int smem_bytes = (D * D + BM * D) * sizeof(float);  // 96 KB
    cudaFuncSetAttribute(fused_gemm_place_kernel,
                         cudaFuncAttributeMaxDynamicSharedMemorySize, smem_bytes);
    fused_gemm_place_kernel<<<T, 256, smem_bytes>>>(x, b, src, dst, w,
                                                    N, E, nb_gemm, nb_place);

    int nb_agg = (N * 32 + 255) / 256;   // one warp per node
    aggregate_kernel<<<nb_agg, 256>>>(out, N);
    fixup_kernel<<<16, 256>>>(out);
}

// round 15
// speedup vs baseline: 1.2396x; 1.0372x over previous
#include <cuda_runtime.h>
#include <cuda_fp16.h>
#include <cstdint>

#define D 128
#define BM 64
#define N_MAX 100000
#define E_MAX 3200000
#define CAP 128          // proven best (R9)

// ---- packed f32x2 helpers --------------------------------------------------
#define FMA_F32X2(d, a, b, c) \
    asm("fma.rn.f32x2 %0, %1, %2, %3;" : "=l"(d) : "l"(a), "l"(b), "l"(c))
#define ADD_F32X2(d, a, b) \
    asm("add.rn.f32x2 %0, %1, %2;" : "=l"(d) : "l"(a), "l"(b))
#define PACK_DUP_F32X2(out, r) \
    asm("mov.b64 %0, {%1, %1};" : "=l"(out) : "r"(r))

static __device__ __forceinline__ unsigned h2_to_u32(__half2 h) {
    return *reinterpret_cast<unsigned*>(&h);
}
static __device__ __forceinline__ __half2 u32_to_h2(unsigned u) {
    return *reinterpret_cast<__half2*>(&u);
}

// Scratch
__device__ uint2  g_hh[N_MAX * 32];          // h in fp16 (4 halves / lane-slot)
__device__ float4 g_wt4[D * D / 4];          // W^T (read via __ldg, L1-resident)
__device__ int    g_cnt[N_MAX];              // per-node cursor
__device__ int2   g_bkt[(long long)N_MAX * CAP];  // (src, w-bits) buckets
__device__ int    g_ovf_cnt;                 // overflow edges (expected 0)
__device__ int4   g_ovf[4096];               // (src, dst, w-bits, pad)

// ---------------------------------------------------------------------------
__global__ void zero_kernel(int n_nodes) {
    int i = blockIdx.x * blockDim.x + threadIdx.x;
    if (i < n_nodes) g_cnt[i] = 0;
    if (i == 0) g_ovf_cnt = 0;
}

__global__ void transpose_w_kernel(const float* __restrict__ W) {
    int idx = blockIdx.x * blockDim.x + threadIdx.x;
    int j = idx >> 7;
    int k = idx & (D - 1);
    ((float*)g_wt4)[k * D + j] = W[j * D + k];
}

// ---------------------------------------------------------------------------
// FUSED kernel, 32KB smem/block (X tile only; W^T streamed via L1 __ldg).
//   b % 3 == 0  -> GEMM tile b/3          (FMA2-pipe-bound)
//   otherwise   -> place chunk            (L2/atomic-bound, high occupancy)
// ---------------------------------------------------------------------------
__device__ __forceinline__ void gemm_block(
    const float* __restrict__ x, const float* __restrict__ bias,
    int n_rows, int blk)
{
    extern __shared__ float4 smem4[];
    float4* Xs4 = smem4;                 // [64][32] f4 = 32KB

    const int tid  = threadIdx.x;
    const int row0 = blk * BM;
    const int rows = min(BM, n_rows - row0);

    {
        const float4* x4 = (const float4*)(x + (long long)row0 * D);
        const int nf4 = rows * (D / 4);
        for (int i = tid; i < nf4; i += 256)
            Xs4[i] = x4[i];
    }
    __syncthreads();

    const int warp = tid >> 5;
    const int lane = tid & 31;
    const int r0 = warp * 8;

    const ulonglong2* Wg = (const ulonglong2*)g_wt4;  // global, L1-cached

    unsigned long long acc[8][2];
    #pragma unroll
    for (int i = 0; i < 8; i++) { acc[i][0] = 0ull; acc[i][1] = 0ull; }

    #pragma unroll 4
    for (int k = 0; k < D; k += 4) {
        ulonglong2 wv0 = __ldg(Wg + (k + 0) * 32 + lane);
        ulonglong2 wv1 = __ldg(Wg + (k + 1) * 32 + lane);
        ulonglong2 wv2 = __ldg(Wg + (k + 2) * 32 + lane);
        ulonglong2 wv3 = __ldg(Wg + (k + 3) * 32 + lane);
        #pragma unroll
        for (int i = 0; i < 8; i++) {
            float4 xv = Xs4[(r0 + i) * 32 + (k >> 2)];  // warp broadcast
            unsigned long long xd;
            PACK_DUP_F32X2(xd, __float_as_uint(xv.x));
            FMA_F32X2(acc[i][0], xd, wv0.x, acc[i][0]);
            FMA_F32X2(acc[i][1], xd, wv0.y, acc[i][1]);
            PACK_DUP_F32X2(xd, __float_as_uint(xv.y));
            FMA_F32X2(acc[i][0], xd, wv1.x, acc[i][0]);
            FMA_F32X2(acc[i][1], xd, wv1.y, acc[i][1]);
            PACK_DUP_F32X2(xd, __float_as_uint(xv.z));
            FMA_F32X2(acc[i][0], xd, wv2.x, acc[i][0]);
            FMA_F32X2(acc[i][1], xd, wv2.y, acc[i][1]);
            PACK_DUP_F32X2(xd, __float_as_uint(xv.w));
            FMA_F32X2(acc[i][0], xd, wv3.x, acc[i][0]);
            FMA_F32X2(acc[i][1], xd, wv3.y, acc[i][1]);
        }
    }

    ulonglong2 bv = ((const ulonglong2*)bias)[lane];
    #pragma unroll
    for (int i = 0; i < 8; i++) {
        int r = r0 + i;
        if (r < rows) {
            ulonglong2 o;
            ADD_F32X2(o.x, acc[i][0], bv.x);
            ADD_F32X2(o.y, acc[i][1], bv.y);
            float2 p0 = *(float2*)&o.x;
            float2 p1 = *(float2*)&o.y;
            uint2 hh;
            hh.x = h2_to_u32(__floats2half2_rn(p0.x, p0.y));
            hh.y = h2_to_u32(__floats2half2_rn(p1.x, p1.y));
            g_hh[(long long)(row0 + r) * 32 + lane] = hh;
        }
    }
}

__device__ __forceinline__ void place_block(
    const int* __restrict__ src, const int* __restrict__ dst,
    const float* __restrict__ w, int n_edges, int pidx)
{
    int t = pidx * 256 + threadIdx.x;
    int e = t * 4;
    #pragma unroll
    for (int j = 0; j < 4; j++) {
        int i = e + j;
        if (i >= n_edges) return;
        int s = src[i];
        int d = dst[i];
        int wb = __float_as_int(w[i]);
        int pos = atomicAdd(&g_cnt[d], 1);
        if (pos < CAP) {
            g_bkt[(long long)d * CAP + pos] = make_int2(s, wb);
        } else {
            int o = atomicAdd(&g_ovf_cnt, 1);
            if (o < 4096) g_ovf[o] = make_int4(s, d, wb, 0);
        }
    }
}

__global__ __launch_bounds__(256)
void fused_gemm_place_kernel(const float* __restrict__ x,
                             const float* __restrict__ bias,
                             const int* __restrict__ src,
                             const int* __restrict__ dst,
                             const float* __restrict__ w,
                             int n_rows, int n_edges,
                             int nb_gemm, int nb_place) {
    int b = blockIdx.x;
    if (b % 3 == 0) {
        int gi = b / 3;
        if (gi < nb_gemm) gemm_block(x, bias, n_rows, gi);
    } else {
        int pi = b - b / 3 - 1;
        if (pi < nb_place) place_block(src, dst, w, n_edges, pi);
    }
}

// ---------------------------------------------------------------------------
// aggregate (R9 shape, measured at its LTS wall 71us): one warp per node.
// ---------------------------------------------------------------------------
__global__ __launch_bounds__(256)
void aggregate_kernel(float* __restrict__ out, int n_nodes) {
    int node = (blockIdx.x * 256 + threadIdx.x) >> 5;
    int lane = threadIdx.x & 31;
    if (node >= n_nodes) return;

    const int2* seg = g_bkt + (long long)node * CAP;
    int cnt = g_cnt[node];
    int end = min(cnt, CAP);

    float4 acc = make_float4(0.f, 0.f, 0.f, 0.f);

    int i = 0;
    for (; i + 8 <= end; i += 8) {
        int2 ed[8];
        uint2 hv[8];
        #pragma unroll
        for (int j = 0; j < 8; j++) ed[j] = seg[i + j];
        #pragma unroll
        for (int j = 0; j < 8; j++) hv[j] = g_hh[(long long)ed[j].x * 32 + lane];
        #pragma unroll
        for (int j = 0; j < 8; j++) {
            float wv = __int_as_float(ed[j].y);
            float2 a  = __half22float2(u32_to_h2(hv[j].x));
            float2 bq = __half22float2(u32_to_h2(hv[j].y));
            acc.x += a.x * wv; acc.y += a.y * wv;
            acc.z += bq.x * wv; acc.w += bq.y * wv;
        }
    }
    for (; i < end; i++) {
        int2 e = seg[i];
        float wv = __int_as_float(e.y);
        uint2 hv = g_hh[(long long)e.x * 32 + lane];
        float2 a  = __half22float2(u32_to_h2(hv.x));
        float2 bq = __half22float2(u32_to_h2(hv.y));
        acc.x += a.x * wv; acc.y += a.y * wv; acc.z += bq.x * wv; acc.w += bq.y * wv;
    }

    ((float4*)out)[(long long)node * 32 + lane] = acc;
}

// ---------------------------------------------------------------------------
__global__ void fixup_kernel(float* __restrict__ out) {
    int n = min(g_ovf_cnt, 4096);
    int lane = threadIdx.x & 31;
    int wid_global = (blockIdx.x * blockDim.x + threadIdx.x) >> 5;
    int nwarps = (gridDim.x * blockDim.x) >> 5;
    for (int e = wid_global; e < n; e += nwarps) {
        int4 ov = g_ovf[e];
        float wv = __int_as_float(ov.z);
        uint2 hv = g_hh[(long long)ov.x * 32 + lane];
        float2 a  = __half22float2(u32_to_h2(hv.x));
        float2 bq = __half22float2(u32_to_h2(hv.y));
        float* p = out + (long long)ov.y * D + lane * 4;
        asm volatile("red.global.add.v4.f32 [%0], {%1, %2, %3, %4};"
                     :: "l"(p), "f"(a.x * wv), "f"(a.y * wv),
                        "f"(bq.x * wv), "f"(bq.y * wv) : "memory");
    }
}

// ---------------------------------------------------------------------------
extern "C" void kernel_launch(void* const* d_in, const int* in_sizes, int n_in,
                              void* d_out, int out_size) {
    const float* x   = (const float*)d_in[0];
    const float* w   = (const float*)d_in[1];
    const float* W   = (const float*)d_in[2];
    const float* b   = (const float*)d_in[3];
    const int*   src = (const int*)d_in[4];   // int32 (JAX x64 disabled)
    const int*   dst = (const int*)d_in[5];

    int N = in_sizes[0] / D;
    int E = in_sizes[1];
    float* out = (float*)d_out;

    int nb_nodes = (N + 255) / 256;
    int nb_gemm  = (N + BM - 1) / BM;              // 1563
    int nb_place = (E + 4 * 256 - 1) / (4 * 256);  // 3125
    int half_p = (nb_place + 1) / 2;
    int T = 3 * (nb_gemm > half_p ? nb_gemm : half_p);

    zero_kernel<<<nb_nodes, 256>>>(N);
    transpose_w_kernel<<<(D * D) / 256, 256>>>(W);

    const int smem_bytes = BM * D * sizeof(float);  // 32 KB (X tile only)
    cudaFuncSetAttribute(fused_gemm_place_kernel,
                         cudaFuncAttributeMaxDynamicSharedMemorySize, smem_bytes);
    fused_gemm_place_kernel<<<T, 256, smem_bytes>>>(x, b, src, dst, w,
                                                    N, E, nb_gemm, nb_place);

    int nb_agg = (N * 32 + 255) / 256;   // one warp per node
    aggregate_kernel<<<nb_agg, 256>>>(out, N);
    fixup_kernel<<<16, 256>>>(out);
}

// round 16
// speedup vs baseline: 1.2467x; 1.0057x over previous
#include <cuda_runtime.h>
#include <cuda_fp16.h>
#include <cstdint>

#define D 128
#define BM 64
#define N_MAX 100000
#define E_MAX 3200000
#define CAP 128          // proven best (R9)

// ---- packed f32x2 helpers --------------------------------------------------
#define FMA_F32X2(d, a, b, c) \
    asm("fma.rn.f32x2 %0, %1, %2, %3;" : "=l"(d) : "l"(a), "l"(b), "l"(c))
#define ADD_F32X2(d, a, b) \
    asm("add.rn.f32x2 %0, %1, %2;" : "=l"(d) : "l"(a), "l"(b))
#define PACK_DUP_F32X2(out, r) \
    asm("mov.b64 %0, {%1, %1};" : "=l"(out) : "r"(r))

static __device__ __forceinline__ unsigned h2_to_u32(__half2 h) {
    return *reinterpret_cast<unsigned*>(&h);
}
static __device__ __forceinline__ __half2 u32_to_h2(unsigned u) {
    return *reinterpret_cast<__half2*>(&u);
}

// L2-only / streaming load hints
static __device__ __forceinline__ uint2 ldcg_u2(const uint2* p) {
    uint2 r;
    asm volatile("ld.global.cg.v2.u32 {%0, %1}, [%2];"
                 : "=r"(r.x), "=r"(r.y) : "l"(p));
    return r;
}
static __device__ __forceinline__ int2 ldcs_i2(const int2* p) {
    int2 r;
    asm volatile("ld.global.cs.v2.s32 {%0, %1}, [%2];"
                 : "=r"(r.x), "=r"(r.y) : "l"(p));
    return r;
}

// Scratch
__device__ uint2  g_hh[N_MAX * 32];          // h in fp16 (4 halves / lane-slot)
__device__ float4 g_wt4[D * D / 4];          // W^T (read via __ldg, L1-resident)
__device__ int    g_cnt[N_MAX];              // per-node cursor
__device__ int2   g_bkt[(long long)N_MAX * CAP];  // (src, w-bits) buckets
__device__ int    g_ovf_cnt;                 // overflow edges (expected 0)
__device__ int4   g_ovf[4096];               // (src, dst, w-bits, pad)

// ---------------------------------------------------------------------------
// prep: blocks [0, nb_zero) zero g_cnt; blocks [nb_zero, +64) transpose W.
// ---------------------------------------------------------------------------
__global__ void prep_kernel(const float* __restrict__ W, int n_nodes, int nb_zero) {
    int b = blockIdx.x;
    if (b < nb_zero) {
        int i = b * 256 + threadIdx.x;
        if (i < n_nodes) g_cnt[i] = 0;
        if (i == 0) g_ovf_cnt = 0;
    } else {
        int idx = (b - nb_zero) * 256 + threadIdx.x;   // 0 .. 16383
        int j = idx >> 7;
        int k = idx & (D - 1);
        ((float*)g_wt4)[k * D + j] = W[j * D + k];
    }
}

// ---------------------------------------------------------------------------
// FUSED kernel (unchanged from R15): 32KB smem, b%3 interleave.
// ---------------------------------------------------------------------------
__device__ __forceinline__ void gemm_block(
    const float* __restrict__ x, const float* __restrict__ bias,
    int n_rows, int blk)
{
    extern __shared__ float4 smem4[];
    float4* Xs4 = smem4;                 // [64][32] f4 = 32KB

    const int tid  = threadIdx.x;
    const int row0 = blk * BM;
    const int rows = min(BM, n_rows - row0);

    {
        const float4* x4 = (const float4*)(x + (long long)row0 * D);
        const int nf4 = rows * (D / 4);
        for (int i = tid; i < nf4; i += 256)
            Xs4[i] = x4[i];
    }
    __syncthreads();

    const int warp = tid >> 5;
    const int lane = tid & 31;
    const int r0 = warp * 8;

    const ulonglong2* Wg = (const ulonglong2*)g_wt4;  // global, L1-cached

    unsigned long long acc[8][2];
    #pragma unroll
    for (int i = 0; i < 8; i++) { acc[i][0] = 0ull; acc[i][1] = 0ull; }

    #pragma unroll 4
    for (int k = 0; k < D; k += 4) {
        ulonglong2 wv0 = __ldg(Wg + (k + 0) * 32 + lane);
        ulonglong2 wv1 = __ldg(Wg + (k + 1) * 32 + lane);
        ulonglong2 wv2 = __ldg(Wg + (k + 2) * 32 + lane);
        ulonglong2 wv3 = __ldg(Wg + (k + 3) * 32 + lane);
        #pragma unroll
        for (int i = 0; i < 8; i++) {
            float4 xv = Xs4[(r0 + i) * 32 + (k >> 2)];  // warp broadcast
            unsigned long long xd;
            PACK_DUP_F32X2(xd, __float_as_uint(xv.x));
            FMA_F32X2(acc[i][0], xd, wv0.x, acc[i][0]);
            FMA_F32X2(acc[i][1], xd, wv0.y, acc[i][1]);
            PACK_DUP_F32X2(xd, __float_as_uint(xv.y));
            FMA_F32X2(acc[i][0], xd, wv1.x, acc[i][0]);
            FMA_F32X2(acc[i][1], xd, wv1.y, acc[i][1]);
            PACK_DUP_F32X2(xd, __float_as_uint(xv.z));
            FMA_F32X2(acc[i][0], xd, wv2.x, acc[i][0]);
            FMA_F32X2(acc[i][1], xd, wv2.y, acc[i][1]);
            PACK_DUP_F32X2(xd, __float_as_uint(xv.w));
            FMA_F32X2(acc[i][0], xd, wv3.x, acc[i][0]);
            FMA_F32X2(acc[i][1], xd, wv3.y, acc[i][1]);
        }
    }

    ulonglong2 bv = ((const ulonglong2*)bias)[lane];
    #pragma unroll
    for (int i = 0; i < 8; i++) {
        int r = r0 + i;
        if (r < rows) {
            ulonglong2 o;
            ADD_F32X2(o.x, acc[i][0], bv.x);
            ADD_F32X2(o.y, acc[i][1], bv.y);
            float2 p0 = *(float2*)&o.x;
            float2 p1 = *(float2*)&o.y;
            uint2 hh;
            hh.x = h2_to_u32(__floats2half2_rn(p0.x, p0.y));
            hh.y = h2_to_u32(__floats2half2_rn(p1.x, p1.y));
            g_hh[(long long)(row0 + r) * 32 + lane] = hh;
        }
    }
}

__device__ __forceinline__ void place_block(
    const int* __restrict__ src, const int* __restrict__ dst,
    const float* __restrict__ w, int n_edges, int pidx)
{
    int t = pidx * 256 + threadIdx.x;
    int e = t * 4;
    #pragma unroll
    for (int j = 0; j < 4; j++) {
        int i = e + j;
        if (i >= n_edges) return;
        int s = src[i];
        int d = dst[i];
        int wb = __float_as_int(w[i]);
        int pos = atomicAdd(&g_cnt[d], 1);
        if (pos < CAP) {
            g_bkt[(long long)d * CAP + pos] = make_int2(s, wb);
        } else {
            int o = atomicAdd(&g_ovf_cnt, 1);
            if (o < 4096) g_ovf[o] = make_int4(s, d, wb, 0);
        }
    }
}

__global__ __launch_bounds__(256)
void fused_gemm_place_kernel(const float* __restrict__ x,
                             const float* __restrict__ bias,
                             const int* __restrict__ src,
                             const int* __restrict__ dst,
                             const float* __restrict__ w,
                             int n_rows, int n_edges,
                             int nb_gemm, int nb_place) {
    int b = blockIdx.x;
    if (b % 3 == 0) {
        int gi = b / 3;
        if (gi < nb_gemm) gemm_block(x, bias, n_rows, gi);
    } else {
        int pi = b - b / 3 - 1;
        if (pi < nb_place) place_block(src, dst, w, n_edges, pi);
    }
}

// ---------------------------------------------------------------------------
// aggregate (R9 shape; gathers via ld.global.cg — L2-only, no L1 allocation;
// seg via ld.global.cs streaming).
// ---------------------------------------------------------------------------
__global__ __launch_bounds__(256)
void aggregate_kernel(float* __restrict__ out, int n_nodes) {
    int node = (blockIdx.x * 256 + threadIdx.x) >> 5;
    int lane = threadIdx.x & 31;
    if (node >= n_nodes) return;

    const int2* seg = g_bkt + (long long)node * CAP;
    int cnt = g_cnt[node];
    int end = min(cnt, CAP);

    float4 acc = make_float4(0.f, 0.f, 0.f, 0.f);

    int i = 0;
    for (; i + 8 <= end; i += 8) {
        int2 ed[8];
        uint2 hv[8];
        #pragma unroll
        for (int j = 0; j < 8; j++) ed[j] = ldcs_i2(seg + i + j);
        #pragma unroll
        for (int j = 0; j < 8; j++)
            hv[j] = ldcg_u2(g_hh + (long long)ed[j].x * 32 + lane);
        #pragma unroll
        for (int j = 0; j < 8; j++) {
            float wv = __int_as_float(ed[j].y);
            float2 a  = __half22float2(u32_to_h2(hv[j].x));
            float2 bq = __half22float2(u32_to_h2(hv[j].y));
            acc.x += a.x * wv; acc.y += a.y * wv;
            acc.z += bq.x * wv; acc.w += bq.y * wv;
        }
    }
    for (; i < end; i++) {
        int2 e = ldcs_i2(seg + i);
        float wv = __int_as_float(e.y);
        uint2 hv = ldcg_u2(g_hh + (long long)e.x * 32 + lane);
        float2 a  = __half22float2(u32_to_h2(hv.x));
        float2 bq = __half22float2(u32_to_h2(hv.y));
        acc.x += a.x * wv; acc.y += a.y * wv; acc.z += bq.x * wv; acc.w += bq.y * wv;
    }

    ((float4*)out)[(long long)node * 32 + lane] = acc;
}

// ---------------------------------------------------------------------------
__global__ void fixup_kernel(float* __restrict__ out) {
    int n = min(g_ovf_cnt, 4096);
    int lane = threadIdx.x & 31;
    int wid_global = (blockIdx.x * blockDim.x + threadIdx.x) >> 5;
    int nwarps = (gridDim.x * blockDim.x) >> 5;
    for (int e = wid_global; e < n; e += nwarps) {
        int4 ov = g_ovf[e];
        float wv = __int_as_float(ov.z);
        uint2 hv = g_hh[(long long)ov.x * 32 + lane];
        float2 a  = __half22float2(u32_to_h2(hv.x));
        float2 bq = __half22float2(u32_to_h2(hv.y));
        float* p = out + (long long)ov.y * D + lane * 4;
        asm volatile("red.global.add.v4.f32 [%0], {%1, %2, %3, %4};"
                     :: "l"(p), "f"(a.x * wv), "f"(a.y * wv),
                        "f"(bq.x * wv), "f"(bq.y * wv) : "memory");
    }
}

// ---------------------------------------------------------------------------
extern "C" void kernel_launch(void* const* d_in, const int* in_sizes, int n_in,
                              void* d_out, int out_size) {
    const float* x   = (const float*)d_in[0];
    const float* w   = (const float*)d_in[1];
    const float* W   = (const float*)d_in[2];
    const float* b   = (const float*)d_in[3];
    const int*   src = (const int*)d_in[4];   // int32 (JAX x64 disabled)
    const int*   dst = (const int*)d_in[5];

    int N = in_sizes[0] / D;
    int E = in_sizes[1];
    float* out = (float*)d_out;

    int nb_zero  = (N + 255) / 256;
    int nb_gemm  = (N + BM - 1) / BM;              // 1563
    int nb_place = (E + 4 * 256 - 1) / (4 * 256);  // 3125
    int half_p = (nb_place + 1) / 2;
    int T = 3 * (nb_gemm > half_p ? nb_gemm : half_p);

    prep_kernel<<<nb_zero + (D * D) / 256, 256>>>(W, N, nb_zero);

    const int smem_bytes = BM * D * sizeof(float);  // 32 KB (X tile only)
    cudaFuncSetAttribute(fused_gemm_place_kernel,
                         cudaFuncAttributeMaxDynamicSharedMemorySize, smem_bytes);
    fused_gemm_place_kernel<<<T, 256, smem_bytes>>>(x, b, src, dst, w,
                                                    N, E, nb_gemm, nb_place);

    int nb_agg = (N * 32 + 255) / 256;   // one warp per node
    aggregate_kernel<<<nb_agg, 256>>>(out, N);
    fixup_kernel<<<16, 256>>>(out);
}